// round 6
// baseline (speedup 1.0000x reference)
#include <cuda_runtime.h>

#define BATCH 512
#define SLEN  1024
#define TAGS  64
#define WARPS_PER_CTA 4
#define THREADS (32 * WARPS_PER_CTA)

// ---------------------------------------------------------------------------
// Packed f32x2 helpers (sm_103a)
// ---------------------------------------------------------------------------
__device__ __forceinline__ unsigned long long ffma2(unsigned long long a,
                                                    unsigned long long b,
                                                    unsigned long long c) {
    unsigned long long d;
    asm("fma.rn.f32x2 %0, %1, %2, %3;" : "=l"(d) : "l"(a), "l"(b), "l"(c));
    return d;
}
__device__ __forceinline__ unsigned long long fadd2(unsigned long long a,
                                                    unsigned long long b) {
    unsigned long long d;
    asm("add.rn.f32x2 %0, %1, %2;" : "=l"(d) : "l"(a), "l"(b));
    return d;
}
__device__ __forceinline__ float2 unpack2(unsigned long long v) {
    float2 f;
    asm("mov.b64 {%0, %1}, %2;" : "=f"(f.x), "=f"(f.y) : "l"(v));
    return f;
}
__device__ __forceinline__ unsigned long long pack2(float lo, float hi) {
    unsigned long long v;
    asm("mov.b64 %0, {%1, %2};" : "=l"(v) : "f"(lo), "f"(hi));
    return v;
}

// ---------------------------------------------------------------------------
// One batch per WARP; lane owns ADJACENT states j0=2*lane, j1=2*lane+1,
// packed into one 64-bit register rp. The per-step alpha exchange is pure
// register traffic: 32x 64-bit shfl delivers input pairs (a_2k, a_2k+1)
// already packed for FFMA2. No shared memory, no barriers, no syncwarp.
//
// Linear-domain recurrence a'[j] = exp(emit[j]) * sum_i a[i]*E[j,i] with
// E = exp(transitions), renormalized EVERY step by the scalar proxy
// a[3] (= lane 1's r1; > 0 always since state 3 is reachable and outside
// all NO_TRANS rows/cols). RCP/LG2 run on MUFU off the critical path;
// exp(emit) is computed one iteration ahead; emissions (float2, states are
// adjacent) prefetched 4 steps ahead.
// ---------------------------------------------------------------------------
__global__ void __launch_bounds__(THREADS, 1)
crf_shfl_kernel(const float* __restrict__ feats,
                const int*   __restrict__ tags,
                const int*   __restrict__ lengths,
                const float* __restrict__ trans,
                const int*   __restrict__ start_p,
                const int*   __restrict__ stop_p,
                float*       __restrict__ out) {
    const int warp = threadIdx.x >> 5;
    const int lane = threadIdx.x & 31;
    const int b    = blockIdx.x * WARPS_PER_CTA + warp;
    const int j0   = 2 * lane;
    const int j1   = 2 * lane + 1;

    const int len   = lengths[b];
    const int start = *start_p;
    const int stop  = *stop_p;

    // Two packed rows of E = exp(trans), pair over adjacent INPUT states:
    // Eq0[k] = (E[j0,2k], E[j0,2k+1]), Eq1[k] = (E[j1,2k], E[j1,2k+1])
    unsigned long long Eq0[TAGS / 2], Eq1[TAGS / 2];
    {
        const float2* t0 = (const float2*)(trans + j0 * TAGS);
        const float2* t1 = (const float2*)(trans + j1 * TAGS);
#pragma unroll
        for (int k = 0; k < 32; k++) {
            float2 v = t0[k];
            Eq0[k] = pack2(__expf(v.x), __expf(v.y));
            float2 w = t1[k];
            Eq1[k] = pack2(__expf(w.x), __expf(w.y));
        }
    }

    const float* fb = feats + (size_t)b * SLEN * TAGS + j0;  // j1 = j0+1

    // ---- step 0 closed form: a1[j] = exp(trans[j,start]) * exp(emit0[j]) ----
    float2 e0 = *(const float2*)fb;
    float r0 = __expf(trans[j0 * TAGS + start]) * __expf(e0.x);
    float r1 = __expf(trans[j1 * TAGS + start]) * __expf(e0.y);
    unsigned long long rp = pack2(r0, r1);
    float C2 = 0.0f;  // accumulated log2 scale (uniform across lanes)

    // Emission prefetch ring (depth 4): entering iter t we hold
    // ex0/ex1 = exp(e_t[j0/j1]); q1..q3 = e_{t+1..t+3} (float2 each).
    float2 ev = *(const float2*)(fb + TAGS);
    float ex0 = __expf(ev.x), ex1 = __expf(ev.y);
    float2 q1 = *(const float2*)(fb + 2 * TAGS);
    float2 q2 = *(const float2*)(fb + 3 * TAGS);
    float2 q3 = *(const float2*)(fb + 4 * TAGS);

#pragma unroll 1
    for (int t = 1; t < len; t++) {
        // ---- off-path work first: renorm scalars + prefetch rotation ----
        float a3  = __shfl_sync(0xFFFFFFFFu, r1, 1);   // state 3, > 0
        float inv = __fdividef(1.0f, a3);              // MUFU.RCP
        C2 += __log2f(a3);                             // MUFU.LG2
        float sc0 = ex0 * inv;
        float sc1 = ex1 * inv;

        ex0 = __expf(q1.x); ex1 = __expf(q1.y);        // exp for step t+1
        q1 = q2; q2 = q3;
        int tp = t + 4; if (tp > SLEN - 1) tp = SLEN - 1;
        q3 = *(const float2*)(fb + (size_t)tp * TAGS);

        // ---- matvec via register all-gather: 32x 64-bit shfl + FFMA2 ----
        unsigned long long c00 = 0ull, c01 = 0ull, c02 = 0ull, c03 = 0ull;
        unsigned long long c10 = 0ull, c11 = 0ull, c12 = 0ull, c13 = 0ull;
#pragma unroll
        for (int k = 0; k < 32; k += 4) {
            unsigned long long ap0 = __shfl_sync(0xFFFFFFFFu, rp, k);
            unsigned long long ap1 = __shfl_sync(0xFFFFFFFFu, rp, k + 1);
            unsigned long long ap2 = __shfl_sync(0xFFFFFFFFu, rp, k + 2);
            unsigned long long ap3 = __shfl_sync(0xFFFFFFFFu, rp, k + 3);
            c00 = ffma2(ap0, Eq0[k],     c00);
            c10 = ffma2(ap0, Eq1[k],     c10);
            c01 = ffma2(ap1, Eq0[k + 1], c01);
            c11 = ffma2(ap1, Eq1[k + 1], c11);
            c02 = ffma2(ap2, Eq0[k + 2], c02);
            c12 = ffma2(ap2, Eq1[k + 2], c12);
            c03 = ffma2(ap3, Eq0[k + 3], c03);
            c13 = ffma2(ap3, Eq1[k + 3], c13);
        }
        float2 f0 = unpack2(fadd2(fadd2(c00, c01), fadd2(c02, c03)));
        float2 f1 = unpack2(fadd2(fadd2(c10, c11), fadd2(c12, c13)));
        r0 = (f0.x + f0.y) * sc0;
        r1 = (f1.x + f1.y) * sc1;
        rp = pack2(r0, r1);
    }

    // ---- gold path score: 32-way strided gather-sum ----
    const int*   tg    = tags  + (size_t)b * SLEN;
    const float* fbase = feats + (size_t)b * SLEN * TAGS;
    float g = 0.0f;
    for (int t = lane; t < len; t += 32) {
        int tn = tg[t];
        int tc = (t == 0) ? start : tg[t - 1];
        g += trans[tn * TAGS + tc] + fbase[(size_t)t * TAGS + tn];
    }

    // ---- alpha = C + log( sum_j a_final[j] * exp(trans[stop, j]) ) ----
    float v = r0 * __expf(trans[stop * TAGS + j0]) +
              r1 * __expf(trans[stop * TAGS + j1]);
#pragma unroll
    for (int off = 16; off > 0; off >>= 1) {
        v += __shfl_xor_sync(0xFFFFFFFFu, v, off);
        g += __shfl_xor_sync(0xFFFFFFFFu, g, off);
    }

    if (lane == 0) {
        int end = tg[len - 1];
        float alpha = C2 * 0.6931471805599453f + __logf(v);
        out[b] = alpha - (g + trans[stop * TAGS + end]);
    }
}

// ---------------------------------------------------------------------------
// Inputs (metadata order):
//   0 feats [B,S,T] f32, 1 tags [B,S] i32, 2 lengths [B] i32,
//   3 masks [B,S] f32 (== t<len, unused), 4 transitions [T,T] f32,
//   5 start_idx i32, 6 stop_idx i32
// ---------------------------------------------------------------------------
extern "C" void kernel_launch(void* const* d_in, const int* in_sizes, int n_in,
                              void* d_out, int out_size) {
    const float* feats   = (const float*)d_in[0];
    const int*   tags    = (const int*)d_in[1];
    const int*   lengths = (const int*)d_in[2];
    const float* trans   = (const float*)d_in[4];
    const int*   start_p = (const int*)d_in[5];
    const int*   stop_p  = (const int*)d_in[6];
    float* out = (float*)d_out;

    crf_shfl_kernel<<<BATCH / WARPS_PER_CTA, THREADS>>>(feats, tags, lengths,
                                                        trans, start_p, stop_p,
                                                        out);
}

// round 7
// speedup vs baseline: 1.4365x; 1.4365x over previous
#include <cuda_runtime.h>

#define BATCH 512
#define SLEN  1024
#define TAGS  64
#define WARPS_PER_CTA 4
#define THREADS (32 * WARPS_PER_CTA)

// ---------------------------------------------------------------------------
// Packed f32x2 + ordered smem helpers (sm_103a)
// ---------------------------------------------------------------------------
__device__ __forceinline__ unsigned long long ffma2(unsigned long long a,
                                                    unsigned long long b,
                                                    unsigned long long c) {
    unsigned long long d;
    asm("fma.rn.f32x2 %0, %1, %2, %3;" : "=l"(d) : "l"(a), "l"(b), "l"(c));
    return d;
}
__device__ __forceinline__ unsigned long long fadd2(unsigned long long a,
                                                    unsigned long long b) {
    unsigned long long d;
    asm("add.rn.f32x2 %0, %1, %2;" : "=l"(d) : "l"(a), "l"(b));
    return d;
}
__device__ __forceinline__ float2 unpack2(unsigned long long v) {
    float2 f;
    asm("mov.b64 {%0, %1}, %2;" : "=f"(f.x), "=f"(f.y) : "l"(v));
    return f;
}
__device__ __forceinline__ unsigned long long pack2(float lo, float hi) {
    unsigned long long v;
    asm("mov.b64 %0, {%1, %2};" : "=l"(v) : "f"(lo), "f"(hi));
    return v;
}
// Ordered (volatile) smem ops: program-order STS -> LDS within one convergent
// warp is the only sync the exchange needs; "memory" clobber stops the
// compiler from reordering across them.
__device__ __forceinline__ void sts64(unsigned addr, unsigned long long v) {
    asm volatile("st.shared.b64 [%0], %1;" :: "r"(addr), "l"(v) : "memory");
}
__device__ __forceinline__ ulonglong2 lds128(unsigned addr) {
    ulonglong2 r;
    asm volatile("ld.shared.v2.b64 {%0, %1}, [%2];"
                 : "=l"(r.x), "=l"(r.y) : "r"(addr) : "memory");
    return r;
}

// ---------------------------------------------------------------------------
// One batch per WARP; lane owns ADJACENT states j0=2*lane, j1=2*lane+1.
// Alpha exchange: one STS.64 per lane -> 16 broadcast LDS.128 per lane.
// No __syncwarp / barriers anywhere: single convergent warp, in-order
// per-warp shared-memory pipeline provides the ordering.
//
// Linear-domain recurrence a'[j] = exp(emit[j]) * sum_i a[i]*E[j,i],
// E = exp(transitions); renormalized every 8 steps by scalar proxy a[3]
// (= lane1.r1, > 0 always: state 3 reachable, outside NO_TRANS rows/cols),
// obtained by a register shfl — RCP/LG2 on MUFU off the critical path.
// exp(emit) computed one step ahead; emissions (LDG.64) prefetched 4 ahead.
// Main loop unrolled x2 with explicit ping-pong buffers.
// ---------------------------------------------------------------------------
__global__ void __launch_bounds__(THREADS, 1)
crf_warp_kernel(const float* __restrict__ feats,
                const int*   __restrict__ tags,
                const int*   __restrict__ lengths,
                const float* __restrict__ trans,
                const int*   __restrict__ start_p,
                const int*   __restrict__ stop_p,
                float*       __restrict__ out) {
    const int warp = threadIdx.x >> 5;
    const int lane = threadIdx.x & 31;
    const int b    = blockIdx.x * WARPS_PER_CTA + warp;
    const int j0   = 2 * lane;
    const int j1   = 2 * lane + 1;

    __shared__ __align__(16) float a_s[WARPS_PER_CTA][2][TAGS];

    const int len   = lengths[b];
    const int start = *start_p;
    const int stop  = *stop_p;

    // Packed rows of E = exp(trans), paired over adjacent input states:
    // Eq0[k] = (E[j0,2k], E[j0,2k+1]), Eq1[k] = (E[j1,2k], E[j1,2k+1])
    unsigned long long Eq0[TAGS / 2], Eq1[TAGS / 2];
    {
        const float2* t0 = (const float2*)(trans + j0 * TAGS);
        const float2* t1 = (const float2*)(trans + j1 * TAGS);
#pragma unroll
        for (int k = 0; k < 32; k++) {
            float2 v = t0[k];
            Eq0[k] = pack2(__expf(v.x), __expf(v.y));
            float2 w = t1[k];
            Eq1[k] = pack2(__expf(w.x), __expf(w.y));
        }
    }

    const float* fb = feats + (size_t)b * SLEN * TAGS + j0;  // j1 = j0 + 1

    const unsigned buf0 = (unsigned)__cvta_generic_to_shared(&a_s[warp][0][0]);
    const unsigned buf1 = (unsigned)__cvta_generic_to_shared(&a_s[warp][1][0]);

    // ---- step 0 closed form: a1[j] = exp(trans[j,start]) * exp(emit0[j]) ----
    float2 e0 = *(const float2*)fb;
    float r0 = __expf(trans[j0 * TAGS + start]) * __expf(e0.x);
    float r1 = __expf(trans[j1 * TAGS + start]) * __expf(e0.y);
    sts64(buf0 + 8u * lane, pack2(r0, r1));
    float C2 = 0.0f;  // accumulated log2 scale (uniform across lanes)

    // Emission prefetch ring (depth 4): entering iter t we hold
    // ex0/ex1 = exp(e_t[j0/j1]); q1..q3 = e_{t+1..t+3}.
    float2 ev = *(const float2*)(fb + TAGS);
    float ex0 = __expf(ev.x), ex1 = __expf(ev.y);
    float2 q1 = *(const float2*)(fb + 2 * TAGS);
    float2 q2 = *(const float2*)(fb + 3 * TAGS);
    float2 q3 = *(const float2*)(fb + 4 * TAGS);

#define CRF_STEP(T, SRC, DST)                                                  \
    {                                                                          \
        float sc0 = ex0, sc1 = ex1;                                            \
        if (((T) & 7) == 7) {                                                  \
            float a3  = __shfl_sync(0xFFFFFFFFu, r1, 1); /* state 3, > 0 */    \
            float inv = __fdividef(1.0f, a3);            /* MUFU.RCP */        \
            sc0 *= inv; sc1 *= inv;                                            \
            C2 += __log2f(a3);                           /* MUFU.LG2 */        \
        }                                                                      \
        ex0 = __expf(q1.x); ex1 = __expf(q1.y);          /* for step T+1 */    \
        q1 = q2; q2 = q3;                                                      \
        int tp_ = (T) + 4; if (tp_ > SLEN - 1) tp_ = SLEN - 1;                 \
        q3 = *(const float2*)(fb + (size_t)tp_ * TAGS);                        \
        unsigned long long c00 = 0ull, c01 = 0ull, c10 = 0ull, c11 = 0ull;     \
        _Pragma("unroll")                                                      \
        for (int k = 0; k < 16; k++) {                                         \
            ulonglong2 ap = lds128((SRC) + 16u * k);                           \
            c00 = ffma2(ap.x, Eq0[2 * k],     c00);                            \
            c10 = ffma2(ap.x, Eq1[2 * k],     c10);                            \
            c01 = ffma2(ap.y, Eq0[2 * k + 1], c01);                            \
            c11 = ffma2(ap.y, Eq1[2 * k + 1], c11);                            \
        }                                                                      \
        float2 f0 = unpack2(fadd2(c00, c01));                                  \
        float2 f1 = unpack2(fadd2(c10, c11));                                  \
        r0 = (f0.x + f0.y) * sc0;                                              \
        r1 = (f1.x + f1.y) * sc1;                                              \
        sts64((DST) + 8u * lane, pack2(r0, r1));                               \
    }

    int t = 1;
#pragma unroll 1
    while (t + 1 < len) {
        CRF_STEP(t,     buf0, buf1);
        CRF_STEP(t + 1, buf1, buf0);
        t += 2;
    }
    if (t < len) {
        CRF_STEP(t, buf0, buf1);
    }
#undef CRF_STEP

    // ---- gold path score: 32-way strided gather-sum ----
    const int*   tg    = tags  + (size_t)b * SLEN;
    const float* fbase = feats + (size_t)b * SLEN * TAGS;
    float g = 0.0f;
    for (int tt = lane; tt < len; tt += 32) {
        int tn = tg[tt];
        int tc = (tt == 0) ? start : tg[tt - 1];
        g += trans[tn * TAGS + tc] + fbase[(size_t)tt * TAGS + tn];
    }

    // ---- alpha = C + log( sum_j a_final[j] * exp(trans[stop, j]) ) ----
    float v = r0 * __expf(trans[stop * TAGS + j0]) +
              r1 * __expf(trans[stop * TAGS + j1]);
#pragma unroll
    for (int off = 16; off > 0; off >>= 1) {
        v += __shfl_xor_sync(0xFFFFFFFFu, v, off);
        g += __shfl_xor_sync(0xFFFFFFFFu, g, off);
    }

    if (lane == 0) {
        int end = tg[len - 1];
        float alpha = C2 * 0.6931471805599453f + __logf(v);
        out[b] = alpha - (g + trans[stop * TAGS + end]);
    }
}

// ---------------------------------------------------------------------------
// Inputs (metadata order):
//   0 feats [B,S,T] f32, 1 tags [B,S] i32, 2 lengths [B] i32,
//   3 masks [B,S] f32 (== t<len, unused), 4 transitions [T,T] f32,
//   5 start_idx i32, 6 stop_idx i32
// ---------------------------------------------------------------------------
extern "C" void kernel_launch(void* const* d_in, const int* in_sizes, int n_in,
                              void* d_out, int out_size) {
    const float* feats   = (const float*)d_in[0];
    const int*   tags    = (const int*)d_in[1];
    const int*   lengths = (const int*)d_in[2];
    const float* trans   = (const float*)d_in[4];
    const int*   start_p = (const int*)d_in[5];
    const int*   stop_p  = (const int*)d_in[6];
    float* out = (float*)d_out;

    crf_warp_kernel<<<BATCH / WARPS_PER_CTA, THREADS>>>(feats, tags, lengths,
                                                        trans, start_p, stop_p,
                                                        out);
}